// round 2
// baseline (speedup 1.0000x reference)
#include <cuda_runtime.h>
#include <cstdint>

// CrossModalCenterLoss:
//   loss = (sum_b clip(||x_b - centers[labels_b]||^2, 1e-12, 1e12)) / B
//        + (C-1) * 1e-12            <- the masked-out zeros, clamped up
//
// Inputs (metadata order): x [B,D] f32, labels [B] int32 (JAX x64-disabled
// downcasts the requested int64), centers [C,D] f32. Output: scalar f32.

#define BATCH_N   4096
#define NUM_CLS   10000
#define FEAT_D    256
#define CLAMP_LO  1e-12f
#define CLAMP_HI  1e12f

__global__ void cmcl_init(float* out) {
    // Contribution of the (C-1) zeroed entries per row, after clamp and /B:
    //   B*(C-1)*CLAMP_LO / B = (C-1)*CLAMP_LO
    out[0] = (float)(NUM_CLS - 1) * CLAMP_LO;
}

__global__ __launch_bounds__(256) void cmcl_main(
    const float* __restrict__ x,
    const int* __restrict__ labels,
    const float* __restrict__ centers,
    float* __restrict__ out)
{
    const int warp_in_blk = threadIdx.x >> 5;
    const int lane        = threadIdx.x & 31;
    const int row         = blockIdx.x * 8 + warp_in_blk;   // 8 warps/block

    float acc = 0.0f;
    if (row < BATCH_N) {
        int lbl = labels[row];
        // Defensive clamp: a mis-typed label must never fault the run.
        lbl = max(0, min(NUM_CLS - 1, lbl));
        const float4* xr = reinterpret_cast<const float4*>(x + (size_t)row * FEAT_D);
        const float4* cr = reinterpret_cast<const float4*>(centers + (size_t)lbl * FEAT_D);

        // 256 floats = 64 float4 per row; 32 lanes x 2 float4 each.
        #pragma unroll
        for (int i = 0; i < 2; i++) {
            float4 a = xr[lane + 32 * i];
            float4 b = cr[lane + 32 * i];
            float d0 = a.x - b.x;
            float d1 = a.y - b.y;
            float d2 = a.z - b.z;
            float d3 = a.w - b.w;
            acc = fmaf(d0, d0, acc);
            acc = fmaf(d1, d1, acc);
            acc = fmaf(d2, d2, acc);
            acc = fmaf(d3, d3, acc);
        }
    }

    // Warp reduction of the per-lane partial sums.
    #pragma unroll
    for (int o = 16; o > 0; o >>= 1)
        acc += __shfl_xor_sync(0xffffffffu, acc, o);

    // acc on lane 0 now = ||x_row - c||^2 for this warp's row.
    __shared__ float warp_sums[8];
    if (lane == 0) {
        float d = fminf(fmaxf(acc, CLAMP_LO), CLAMP_HI);
        warp_sums[warp_in_blk] = d * (1.0f / (float)BATCH_N);
    }
    __syncthreads();

    // Warp 0 reduces the 8 per-warp values, one atomic per block.
    if (warp_in_blk == 0) {
        float v = (lane < 8) ? warp_sums[lane] : 0.0f;
        #pragma unroll
        for (int o = 4; o > 0; o >>= 1)
            v += __shfl_xor_sync(0xffffffffu, v, o);
        if (lane == 0)
            atomicAdd(out, v);
    }
}

extern "C" void kernel_launch(void* const* d_in, const int* in_sizes, int n_in,
                              void* d_out, int out_size) {
    const float* x       = (const float*)d_in[0];
    const int*   labels  = (const int*)d_in[1];
    const float* centers = (const float*)d_in[2];
    float*       out     = (float*)d_out;
    (void)in_sizes; (void)n_in; (void)out_size;

    cmcl_init<<<1, 1>>>(out);
    cmcl_main<<<(BATCH_N + 7) / 8, 256>>>(x, labels, centers, out);
}